// round 1
// baseline (speedup 1.0000x reference)
#include <cuda_runtime.h>
#include <cstdint>

// C = triu(A @ B), A and B upper-triangular fp32, N = 4096.
// Because inputs are exactly upper-triangular, C[i][j] for i>j is a sum of
// exact-zero products; within diagonal blocks the computed lower part is
// exactly 0.0f. Blocks strictly below the diagonal are zero-filled directly.
//
// Classic register-blocked SGEMM: 128x128 CTA tile, BK=8, 8x8 per thread,
// float4 global loads/stores, transposed A in smem for vectorized LDS.
// K-loop restricted to [bi*128, (bj+1)*128) — the only k where both
// A[i][k] and B[k][j] can be nonzero for this tile.

#define TN_N 4096
#define BM 128
#define BN 128
#define BK 8
#define TM 8
#define TT 8   // TN per thread (renamed to avoid clash)

__global__ __launch_bounds__(256, 2)
void triu_mm_kernel(const float* __restrict__ A,
                    const float* __restrict__ B,
                    float* __restrict__ C) {
    const int bj = blockIdx.x;       // column block
    const int bi = blockIdx.y;       // row block
    const int rowBase = bi * BM;
    const int colBase = bj * BN;
    const int tid = threadIdx.x;

    if (bi > bj) {
        // Strictly-lower block: output is exactly zero. 128*128 floats =
        // 4096 float4; 256 threads -> 16 stores each.
        const float4 z = make_float4(0.f, 0.f, 0.f, 0.f);
        #pragma unroll
        for (int it = 0; it < (BM * BN / 4) / 256; ++it) {
            int idx = it * 256 + tid;          // float4 index in tile
            int r   = idx / (BN / 4);
            int c4  = idx % (BN / 4);
            *reinterpret_cast<float4*>(
                C + (size_t)(rowBase + r) * TN_N + colBase + c4 * 4) = z;
        }
        return;
    }

    __shared__ float As[BK][BM];   // transposed: As[k][m]
    __shared__ float Bs[BK][BN];

    const int tx = tid % (BN / TT);   // 0..15 (col group)
    const int ty = tid / (BN / TT);   // 0..15 (row group)

    float acc[TM][TT] = {};
    float aReg[TM], bReg[TT];

    // A tile load: BM x BK = 128x8 floats = 256 float4, one per thread.
    const int aRow  = tid / (BK / 4);   // 0..127
    const int aCol4 = tid % (BK / 4);   // 0..1
    // B tile load: BK x BN = 8x128 floats = 256 float4, one per thread.
    const int bRow  = tid / (BN / 4);   // 0..7
    const int bCol4 = tid % (BN / 4);   // 0..31

    const int kStart = rowBase;          // k >= min i of this tile
    const int kEnd   = colBase + BN;     // k <= max j of this tile (excl.)

    const float* aPtr = A + (size_t)(rowBase + aRow) * TN_N + aCol4 * 4;
    const float* bPtr = B + colBase + bCol4 * 4;

    for (int k0 = kStart; k0 < kEnd; k0 += BK) {
        float4 av = *reinterpret_cast<const float4*>(aPtr + k0);
        float4 bv = *reinterpret_cast<const float4*>(
            bPtr + (size_t)(k0 + bRow) * TN_N);

        As[aCol4 * 4 + 0][aRow] = av.x;
        As[aCol4 * 4 + 1][aRow] = av.y;
        As[aCol4 * 4 + 2][aRow] = av.z;
        As[aCol4 * 4 + 3][aRow] = av.w;
        *reinterpret_cast<float4*>(&Bs[bRow][bCol4 * 4]) = bv;
        __syncthreads();

        #pragma unroll
        for (int kk = 0; kk < BK; ++kk) {
            // vectorized LDS: contiguous 8 floats per operand
            *reinterpret_cast<float4*>(&aReg[0]) =
                *reinterpret_cast<const float4*>(&As[kk][ty * TM]);
            *reinterpret_cast<float4*>(&aReg[4]) =
                *reinterpret_cast<const float4*>(&As[kk][ty * TM + 4]);
            *reinterpret_cast<float4*>(&bReg[0]) =
                *reinterpret_cast<const float4*>(&Bs[kk][tx * TT]);
            *reinterpret_cast<float4*>(&bReg[4]) =
                *reinterpret_cast<const float4*>(&Bs[kk][tx * TT + 4]);
            #pragma unroll
            for (int m = 0; m < TM; ++m)
                #pragma unroll
                for (int n = 0; n < TT; ++n)
                    acc[m][n] = fmaf(aReg[m], bReg[n], acc[m][n]);
        }
        __syncthreads();
    }

    #pragma unroll
    for (int m = 0; m < TM; ++m) {
        const int r = rowBase + ty * TM + m;
        float* cRow = C + (size_t)r * TN_N + colBase + tx * TT;
        #pragma unroll
        for (int n = 0; n < TT; n += 4) {
            float4 v = make_float4(acc[m][n], acc[m][n + 1],
                                   acc[m][n + 2], acc[m][n + 3]);
            *reinterpret_cast<float4*>(cRow + n) = v;
        }
    }
}

extern "C" void kernel_launch(void* const* d_in, const int* in_sizes, int n_in,
                              void* d_out, int out_size) {
    const float* A = (const float*)d_in[0];
    const float* B = (const float*)d_in[1];
    float* C = (float*)d_out;

    dim3 grid(TN_N / BN, TN_N / BM);   // (32, 32); y=0 (longest tiles) first
    dim3 block(256);
    triu_mm_kernel<<<grid, block>>>(A, B, C);
}

// round 4
// speedup vs baseline: 1.8797x; 1.8797x over previous
#include <cuda_runtime.h>
#include <cstdint>

// C = triu(A @ B), A,B upper-triangular fp32, N=4096, sm_103 (base target —
// tcgen05 unavailable; harness compiles PTX at .target sm_103).
//
// Legacy tensor path: mma.sync.m16n8k8 tf32 (sm_80 base ISA) with 3-product
// split for fp32-class accuracy:
//   hi = x & 0xFFFFE000 (exact), lo = tf32(x - hi)
//   C  = Ahi*Bhi + Ahi*Blo + Alo*Bhi     (dropped lo*lo ~ 2^-26)
//
// 128x128 CTA tile, 256 thr = 8 warps of 64x32, BK=16 double-buffered smem,
// register-staged global prefetch. Conflict-free LDS via pitch choice:
// A pitch 20 words, B pitch 136 words. Triangular block skipping: tile
// (bi,bj) needs only k in [bi*128, (bj+1)*128). Longest tiles first;
// strictly-lower blocks zero-filled by tail CTAs.

#define NN 4096
#define BK 16
#define THREADS 256
#define N_WORK 528
#define N_ZERO 496

#define APITCH 20                     // words per A row (16 + 4 pad)
#define BPITCH 136                    // words per B row (128 + 8 pad)
#define A_SZ (128 * APITCH)           // 2560 floats
#define B_SZ (BK * BPITCH)            // 2176 floats
#define OAHI 0
#define OALO A_SZ
#define OBHI (2 * A_SZ)
#define OBLO (2 * A_SZ + B_SZ)
#define BUF_FLOATS (2 * A_SZ + 2 * B_SZ)      // 9472
#define SMEM_BYTES (2 * BUF_FLOATS * 4)       // 75776

static __device__ __forceinline__ float tf32hi(float x) {
    return __uint_as_float(__float_as_uint(x) & 0xFFFFE000u);
}
static __device__ __forceinline__ uint32_t tf32lo(float x, float hi) {
    float r;
    asm("cvt.rna.tf32.f32 %0, %1;" : "=f"(r) : "f"(x - hi));
    return __float_as_uint(r);
}
static __device__ __forceinline__ void mma8(float* d, const uint32_t* a,
                                            const uint32_t* b) {
    asm volatile(
        "mma.sync.aligned.m16n8k8.row.col.f32.tf32.tf32.f32 "
        "{%0,%1,%2,%3}, {%4,%5,%6,%7}, {%8,%9}, {%0,%1,%2,%3};"
        : "+f"(d[0]), "+f"(d[1]), "+f"(d[2]), "+f"(d[3])
        : "r"(a[0]), "r"(a[1]), "r"(a[2]), "r"(a[3]), "r"(b[0]), "r"(b[1]));
}

__global__ __launch_bounds__(THREADS, 1)
void triu_mm_mma(const float* __restrict__ A, const float* __restrict__ B,
                 float* __restrict__ C) {
    const int t = blockIdx.x;
    const int tid = threadIdx.x;

    if (t >= N_WORK) {
        // Strictly-lower 128x128 block: output exactly zero.
        int rem = t - N_WORK, bi = 0, bj = 0;
        #pragma unroll 1
        for (int db = 1; db < 32; ++db) {
            int c = 32 - db;
            if (rem < c) { bj = rem; bi = rem + db; break; }
            rem -= c;
        }
        const float4 z = make_float4(0.f, 0.f, 0.f, 0.f);
        const int rowBase = bi * 128, colBase = bj * 128;
        #pragma unroll
        for (int it = 0; it < 16; ++it) {
            int idx = it * 256 + tid;
            int r = idx >> 5, c4 = idx & 31;
            *reinterpret_cast<float4*>(
                C + (size_t)(rowBase + r) * NN + colBase + c4 * 4) = z;
        }
        return;
    }

    // Work block t -> (bi,bj), longest K-span first.
    int bi = 0, bj = 0;
    {
        int rem = t;
        #pragma unroll 1
        for (int d = 31; d >= 0; --d) {
            int c = 32 - d;
            if (rem < c) { bi = rem; bj = rem + d; break; }
            rem -= c;
        }
    }
    const int rowBase = bi * 128, colBase = bj * 128;
    const int kStart = rowBase, kEnd = colBase + 128;

    extern __shared__ float smem[];

    const int lane = tid & 31, wid = tid >> 5;
    const int wm = (wid & 1) * 64;        // warp m-offset in CTA tile
    const int wn = (wid >> 1) * 32;       // warp n-offset
    const int g = lane >> 2, tq = lane & 3;

    // Loader mappings (2 tasks each for A and B per thread).
    const int am0 = tid >> 2, aq0 = tid & 3;          // task = tid
    const int am1 = (tid + 256) >> 2, aq1 = aq0;      // task = tid + 256
    const int bk0 = tid >> 5, bn40 = tid & 31;
    const int bk1 = (tid + 256) >> 5, bn41 = bn40;

    float acc[4][4][4];
    #pragma unroll
    for (int mt = 0; mt < 4; ++mt)
        #pragma unroll
        for (int nt = 0; nt < 4; ++nt)
            #pragma unroll
            for (int i = 0; i < 4; ++i) acc[mt][nt][i] = 0.f;

    float4 pa0, pa1, pb0, pb1;

    // Prefetch first tile.
    {
        const float* ab = A + (size_t)rowBase * NN + kStart;
        pa0 = *reinterpret_cast<const float4*>(ab + (size_t)am0 * NN + aq0 * 4);
        pa1 = *reinterpret_cast<const float4*>(ab + (size_t)am1 * NN + aq1 * 4);
        const float* bb = B + (size_t)kStart * NN + colBase;
        pb0 = *reinterpret_cast<const float4*>(bb + (size_t)bk0 * NN + bn40 * 4);
        pb1 = *reinterpret_cast<const float4*>(bb + (size_t)bk1 * NN + bn41 * 4);
    }

    const int nSteps = (kEnd - kStart) / BK;
    int curBuf = 0;

    // Store first tile (split hi/lo) into buffer 0.
    {
        float* buf = smem;
        float4 h, v;
        uint32_t l[4];
        v = pa0;
        h.x = tf32hi(v.x); h.y = tf32hi(v.y); h.z = tf32hi(v.z); h.w = tf32hi(v.w);
        l[0] = tf32lo(v.x, h.x); l[1] = tf32lo(v.y, h.y);
        l[2] = tf32lo(v.z, h.z); l[3] = tf32lo(v.w, h.w);
        *reinterpret_cast<float4*>(buf + OAHI + am0 * APITCH + aq0 * 4) = h;
        *reinterpret_cast<uint4*>(buf + OALO + am0 * APITCH + aq0 * 4) =
            make_uint4(l[0], l[1], l[2], l[3]);
        v = pa1;
        h.x = tf32hi(v.x); h.y = tf32hi(v.y); h.z = tf32hi(v.z); h.w = tf32hi(v.w);
        l[0] = tf32lo(v.x, h.x); l[1] = tf32lo(v.y, h.y);
        l[2] = tf32lo(v.z, h.z); l[3] = tf32lo(v.w, h.w);
        *reinterpret_cast<float4*>(buf + OAHI + am1 * APITCH + aq1 * 4) = h;
        *reinterpret_cast<uint4*>(buf + OALO + am1 * APITCH + aq1 * 4) =
            make_uint4(l[0], l[1], l[2], l[3]);
        v = pb0;
        h.x = tf32hi(v.x); h.y = tf32hi(v.y); h.z = tf32hi(v.z); h.w = tf32hi(v.w);
        l[0] = tf32lo(v.x, h.x); l[1] = tf32lo(v.y, h.y);
        l[2] = tf32lo(v.z, h.z); l[3] = tf32lo(v.w, h.w);
        *reinterpret_cast<float4*>(buf + OBHI + bk0 * BPITCH + bn40 * 4) = h;
        *reinterpret_cast<uint4*>(buf + OBLO + bk0 * BPITCH + bn40 * 4) =
            make_uint4(l[0], l[1], l[2], l[3]);
        v = pb1;
        h.x = tf32hi(v.x); h.y = tf32hi(v.y); h.z = tf32hi(v.z); h.w = tf32hi(v.w);
        l[0] = tf32lo(v.x, h.x); l[1] = tf32lo(v.y, h.y);
        l[2] = tf32lo(v.z, h.z); l[3] = tf32lo(v.w, h.w);
        *reinterpret_cast<float4*>(buf + OBHI + bk1 * BPITCH + bn41 * 4) = h;
        *reinterpret_cast<uint4*>(buf + OBLO + bk1 * BPITCH + bn41 * 4) =
            make_uint4(l[0], l[1], l[2], l[3]);
    }
    __syncthreads();

    #pragma unroll 1
    for (int step = 0; step < nSteps; ++step) {
        const int kNext = kStart + (step + 1) * BK;
        const bool hasNext = (step + 1) < nSteps;

        // Prefetch next tile into registers.
        if (hasNext) {
            const float* ab = A + (size_t)rowBase * NN + kNext;
            pa0 = *reinterpret_cast<const float4*>(ab + (size_t)am0 * NN + aq0 * 4);
            pa1 = *reinterpret_cast<const float4*>(ab + (size_t)am1 * NN + aq1 * 4);
            const float* bb = B + (size_t)kNext * NN + colBase;
            pb0 = *reinterpret_cast<const float4*>(bb + (size_t)bk0 * NN + bn40 * 4);
            pb1 = *reinterpret_cast<const float4*>(bb + (size_t)bk1 * NN + bn41 * 4);
        }

        // Compute on current buffer: 2 k8 sub-steps.
        const float* buf = smem + curBuf * BUF_FLOATS;
        #pragma unroll
        for (int s = 0; s < 2; ++s) {
            uint32_t ah[4][4], al[4][4], bh[4][2], bl[4][2];
            const int kk = s * 8 + tq;
            #pragma unroll
            for (int mt = 0; mt < 4; ++mt) {
                const int r0 = wm + mt * 16 + g;
                ah[mt][0] = __float_as_uint(buf[OAHI + r0 * APITCH + kk]);
                ah[mt][1] = __float_as_uint(buf[OAHI + (r0 + 8) * APITCH + kk]);
                ah[mt][2] = __float_as_uint(buf[OAHI + r0 * APITCH + kk + 4]);
                ah[mt][3] = __float_as_uint(buf[OAHI + (r0 + 8) * APITCH + kk + 4]);
                al[mt][0] = __float_as_uint(buf[OALO + r0 * APITCH + kk]);
                al[mt][1] = __float_as_uint(buf[OALO + (r0 + 8) * APITCH + kk]);
                al[mt][2] = __float_as_uint(buf[OALO + r0 * APITCH + kk + 4]);
                al[mt][3] = __float_as_uint(buf[OALO + (r0 + 8) * APITCH + kk + 4]);
            }
            #pragma unroll
            for (int nt = 0; nt < 4; ++nt) {
                const int c0 = wn + nt * 8 + g;
                bh[nt][0] = __float_as_uint(buf[OBHI + (s * 8 + tq) * BPITCH + c0]);
                bh[nt][1] = __float_as_uint(buf[OBHI + (s * 8 + tq + 4) * BPITCH + c0]);
                bl[nt][0] = __float_as_uint(buf[OBLO + (s * 8 + tq) * BPITCH + c0]);
                bl[nt][1] = __float_as_uint(buf[OBLO + (s * 8 + tq + 4) * BPITCH + c0]);
            }
            // 3 passes of 16 independent mmas (no back-to-back acc RAW).
            #pragma unroll
            for (int mt = 0; mt < 4; ++mt)
                #pragma unroll
                for (int nt = 0; nt < 4; ++nt)
                    mma8(acc[mt][nt], ah[mt], bh[nt]);
            #pragma unroll
            for (int mt = 0; mt < 4; ++mt)
                #pragma unroll
                for (int nt = 0; nt < 4; ++nt)
                    mma8(acc[mt][nt], ah[mt], bl[nt]);
            #pragma unroll
            for (int mt = 0; mt < 4; ++mt)
                #pragma unroll
                for (int nt = 0; nt < 4; ++nt)
                    mma8(acc[mt][nt], al[mt], bh[nt]);
        }

        // Stage next tile into the other buffer.
        if (hasNext) {
            float* nb = smem + (curBuf ^ 1) * BUF_FLOATS;
            float4 h, v;
            uint32_t l[4];
            v = pa0;
            h.x = tf32hi(v.x); h.y = tf32hi(v.y); h.z = tf32hi(v.z); h.w = tf32hi(v.w);
            l[0] = tf32lo(v.x, h.x); l[1] = tf32lo(v.y, h.y);
            l[2] = tf32lo(v.z, h.z); l[3] = tf32lo(v.w, h.w);
            *reinterpret_cast<float4*>(nb + OAHI + am0 * APITCH + aq0 * 4) = h;
            *reinterpret_cast<uint4*>(nb + OALO + am0 * APITCH + aq0 * 4) =
                make_uint4(l[0], l[1], l[2], l[3]);
            v = pa1;
            h.x = tf32hi(v.x); h.y = tf32hi(v.y); h.z = tf32hi(v.z); h.w = tf32hi(v.w);
            l[0] = tf32lo(v.x, h.x); l[1] = tf32lo(v.y, h.y);
            l[2] = tf32lo(v.z, h.z); l[3] = tf32lo(v.w, h.w);
            *reinterpret_cast<float4*>(nb + OAHI + am1 * APITCH + aq1 * 4) = h;
            *reinterpret_cast<uint4*>(nb + OALO + am1 * APITCH + aq1 * 4) =
                make_uint4(l[0], l[1], l[2], l[3]);
            v = pb0;
            h.x = tf32hi(v.x); h.y = tf32hi(v.y); h.z = tf32hi(v.z); h.w = tf32hi(v.w);
            l[0] = tf32lo(v.x, h.x); l[1] = tf32lo(v.y, h.y);
            l[2] = tf32lo(v.z, h.z); l[3] = tf32lo(v.w, h.w);
            *reinterpret_cast<float4*>(nb + OBHI + bk0 * BPITCH + bn40 * 4) = h;
            *reinterpret_cast<uint4*>(nb + OBLO + bk0 * BPITCH + bn40 * 4) =
                make_uint4(l[0], l[1], l[2], l[3]);
            v = pb1;
            h.x = tf32hi(v.x); h.y = tf32hi(v.y); h.z = tf32hi(v.z); h.w = tf32hi(v.w);
            l[0] = tf32lo(v.x, h.x); l[1] = tf32lo(v.y, h.y);
            l[2] = tf32lo(v.z, h.z); l[3] = tf32lo(v.w, h.w);
            *reinterpret_cast<float4*>(nb + OBHI + bk1 * BPITCH + bn41 * 4) = h;
            *reinterpret_cast<uint4*>(nb + OBLO + bk1 * BPITCH + bn41 * 4) =
                make_uint4(l[0], l[1], l[2], l[3]);
            curBuf ^= 1;
        }
        __syncthreads();
    }

    // Epilogue: fragment layout direct to global. c0,c1 -> (row g, col 2t..),
    // c2,c3 -> (row g+8). float2 stores, 8B aligned, sector-coalesced.
    #pragma unroll
    for (int mt = 0; mt < 4; ++mt) {
        #pragma unroll
        for (int nt = 0; nt < 4; ++nt) {
            const int r0 = rowBase + wm + mt * 16 + g;
            const int c0 = colBase + wn + nt * 8 + tq * 2;
            float2 v01 = make_float2(acc[mt][nt][0], acc[mt][nt][1]);
            float2 v23 = make_float2(acc[mt][nt][2], acc[mt][nt][3]);
            *reinterpret_cast<float2*>(C + (size_t)r0 * NN + c0) = v01;
            *reinterpret_cast<float2*>(C + (size_t)(r0 + 8) * NN + c0) = v23;
        }
    }
}

extern "C" void kernel_launch(void* const* d_in, const int* in_sizes, int n_in,
                              void* d_out, int out_size) {
    const float* A = (const float*)d_in[0];
    const float* B = (const float*)d_in[1];
    float* C = (float*)d_out;

    cudaFuncSetAttribute(triu_mm_mma,
                         cudaFuncAttributeMaxDynamicSharedMemorySize, SMEM_BYTES);
    triu_mm_mma<<<N_WORK + N_ZERO, THREADS, SMEM_BYTES>>>(A, B, C);
}